// round 2
// baseline (speedup 1.0000x reference)
#include <cuda_runtime.h>

#define NUM_EXPERTS 8
#define HIDDEN     1024
#define INTER      1024
#define M_TOK      2048
#define TOPK       2
#define NSLOT      4096        // M_TOK * TOPK
#define N_GU       2048        // 2*INTER
#define MAX_TILES  40          // sum ceil(c_e/128) <= 4096/128 + 8 = 40

// ---------------- device scratch (no allocations allowed) ----------------
__device__ int   g_perm[NSLOT];          // permuted pos -> slot id
__device__ float g_w[NSLOT];             // permuted pos -> routing weight
__device__ int4  g_work[MAX_TILES];      // {expert, rowStart(permuted), rows, 0}
__device__ float g_inter[(size_t)NSLOT * INTER];   // 16 MB
__device__ float g_down [(size_t)NSLOT * HIDDEN];  // 16 MB, indexed by ORIGINAL slot

// ---------------- routing: counts, segments, perm, worklist ----------------
__global__ void route_kernel(const int* __restrict__ ridx,
                             const float* __restrict__ rw) {
    __shared__ int cnt[NUM_EXPERTS];
    __shared__ int ofs[NUM_EXPERTS];
    __shared__ int cur[NUM_EXPERTS];
    int t = threadIdx.x;
    if (t < NUM_EXPERTS) cnt[t] = 0;
    __syncthreads();
    for (int s = t; s < NSLOT; s += blockDim.x)
        atomicAdd(&cnt[ridx[s]], 1);
    __syncthreads();
    if (t == 0) {
        int acc = 0;
        for (int e = 0; e < NUM_EXPERTS; e++) { ofs[e] = acc; cur[e] = acc; acc += cnt[e]; }
    }
    __syncthreads();
    for (int s = t; s < NSLOT; s += blockDim.x) {
        int e = ridx[s];
        int p = atomicAdd(&cur[e], 1);
        g_perm[p] = s;
        g_w[p]    = rw[(s >> 1) * NUM_EXPERTS + e];
    }
    if (t == 0) {
        int n = 0;
        for (int e = 0; e < NUM_EXPERTS; e++) {
            for (int r = 0; r < cnt[e]; r += 128) {
                g_work[n] = make_int4(e, ofs[e] + r, min(128, cnt[e] - r), 0);
                n++;
            }
        }
        for (; n < MAX_TILES; n++) g_work[n] = make_int4(0, 0, 0, 0);
    }
}

// ---------------- grouped SGEMM1: x @ Wgu[e] + bias -> SwiGLU -> g_inter ----
// BM=128, BN=128, BK=8, 256 threads, 8x8 per-thread tile.
__global__ __launch_bounds__(256, 2)
void gemm1_kernel(const float* __restrict__ x,
                  const float* __restrict__ W,      // [E, 1024, 2048]
                  const float* __restrict__ bias) { // [E, 2048]
    int4 wk = g_work[blockIdx.x];
    int rows = wk.z;
    if (rows == 0) return;
    int e = wk.x, rowStart = wk.y;
    int n0 = blockIdx.y * 128;

    __shared__ float As[8][128];
    __shared__ float Bs[8][128];

    int tid  = threadIdx.x;
    int arow = tid >> 1, aq = tid & 1;
    bool avalid = arow < rows;
    const float* aptr = x;                 // dummy base when invalid
    if (avalid) {
        int slot = g_perm[rowStart + arow];
        aptr = x + (size_t)(slot >> 1) * HIDDEN + aq * 4;
    }
    int brow = tid >> 5, bcol = (tid & 31) * 4;
    const float* bptr = W + (size_t)e * HIDDEN * N_GU + (size_t)brow * N_GU + n0 + bcol;

    int tx = tid & 15, ty = tid >> 4;
    float acc[8][8];
    #pragma unroll
    for (int i = 0; i < 8; i++)
        #pragma unroll
        for (int j = 0; j < 8; j++) acc[i][j] = 0.f;

    for (int kk = 0; kk < HIDDEN; kk += 8) {
        float4 a = avalid ? *(const float4*)(aptr + kk) : make_float4(0.f, 0.f, 0.f, 0.f);
        float4 b = *(const float4*)(bptr + (size_t)kk * N_GU);
        __syncthreads();
        As[aq * 4 + 0][arow] = a.x;
        As[aq * 4 + 1][arow] = a.y;
        As[aq * 4 + 2][arow] = a.z;
        As[aq * 4 + 3][arow] = a.w;
        *(float4*)&Bs[brow][bcol] = b;
        __syncthreads();
        #pragma unroll
        for (int k = 0; k < 8; k++) {
            float ar[8], br[8];
            *(float4*)(ar)     = *(const float4*)&As[k][ty * 8];
            *(float4*)(ar + 4) = *(const float4*)&As[k][ty * 8 + 4];
            *(float4*)(br)     = *(const float4*)&Bs[k][tx * 8];
            *(float4*)(br + 4) = *(const float4*)&Bs[k][tx * 8 + 4];
            #pragma unroll
            for (int i = 0; i < 8; i++)
                #pragma unroll
                for (int j = 0; j < 8; j++)
                    acc[i][j] += ar[i] * br[j];
        }
    }

    // bias + SwiGLU, write 4 inter cols per thread-row
    float bl[8];
    #pragma unroll
    for (int j = 0; j < 8; j++)
        bl[j] = bias[e * N_GU + n0 + tx * 8 + j];

    int icol0 = (n0 >> 1) + tx * 4;
    #pragma unroll
    for (int i = 0; i < 8; i++) {
        int lr = ty * 8 + i;
        if (lr >= rows) continue;
        int r = rowStart + lr;
        float* orow = g_inter + (size_t)r * INTER + icol0;
        #pragma unroll
        for (int jj = 0; jj < 4; jj++) {
            float gate = acc[i][2 * jj]     + bl[2 * jj];
            float up   = acc[i][2 * jj + 1] + bl[2 * jj + 1];
            gate = fminf(gate, 7.0f);
            up   = fminf(fmaxf(up, -7.0f), 7.0f);
            float glu = gate / (1.0f + __expf(-1.702f * gate));
            orow[jj] = (up + 1.0f) * glu;
        }
    }
}

// ---------------- grouped SGEMM2: inter @ Wd[e] + bias, * w -> g_down[slot] -
__global__ __launch_bounds__(256, 2)
void gemm2_kernel(const float* __restrict__ W,      // [E, 1024, 1024]
                  const float* __restrict__ bias) { // [E, 1024]
    int4 wk = g_work[blockIdx.x];
    int rows = wk.z;
    if (rows == 0) return;
    int e = wk.x, rowStart = wk.y;
    int n0 = blockIdx.y * 128;

    __shared__ float As[8][128];
    __shared__ float Bs[8][128];

    int tid  = threadIdx.x;
    int arow = tid >> 1, aq = tid & 1;
    bool avalid = arow < rows;
    const float* aptr = g_inter + (size_t)(rowStart + (avalid ? arow : 0)) * INTER + aq * 4;
    int brow = tid >> 5, bcol = (tid & 31) * 4;
    const float* bptr = W + (size_t)e * INTER * HIDDEN + (size_t)brow * HIDDEN + n0 + bcol;

    int tx = tid & 15, ty = tid >> 4;
    float acc[8][8];
    #pragma unroll
    for (int i = 0; i < 8; i++)
        #pragma unroll
        for (int j = 0; j < 8; j++) acc[i][j] = 0.f;

    for (int kk = 0; kk < INTER; kk += 8) {
        float4 a = avalid ? *(const float4*)(aptr + kk) : make_float4(0.f, 0.f, 0.f, 0.f);
        float4 b = *(const float4*)(bptr + (size_t)kk * HIDDEN);
        __syncthreads();
        As[aq * 4 + 0][arow] = a.x;
        As[aq * 4 + 1][arow] = a.y;
        As[aq * 4 + 2][arow] = a.z;
        As[aq * 4 + 3][arow] = a.w;
        *(float4*)&Bs[brow][bcol] = b;
        __syncthreads();
        #pragma unroll
        for (int k = 0; k < 8; k++) {
            float ar[8], br[8];
            *(float4*)(ar)     = *(const float4*)&As[k][ty * 8];
            *(float4*)(ar + 4) = *(const float4*)&As[k][ty * 8 + 4];
            *(float4*)(br)     = *(const float4*)&Bs[k][tx * 8];
            *(float4*)(br + 4) = *(const float4*)&Bs[k][tx * 8 + 4];
            #pragma unroll
            for (int i = 0; i < 8; i++)
                #pragma unroll
                for (int j = 0; j < 8; j++)
                    acc[i][j] += ar[i] * br[j];
        }
    }

    float bl[8];
    #pragma unroll
    for (int j = 0; j < 8; j++)
        bl[j] = bias[e * HIDDEN + n0 + tx * 8 + j];

    #pragma unroll
    for (int i = 0; i < 8; i++) {
        int lr = ty * 8 + i;
        if (lr >= rows) continue;
        int r    = rowStart + lr;
        int slot = g_perm[r];
        float w  = g_w[r];
        float* orow = g_down + (size_t)slot * HIDDEN + n0 + tx * 8;
        #pragma unroll
        for (int j = 0; j < 8; j++)
            orow[j] = (acc[i][j] + bl[j]) * w;
    }
}

// ---------------- deterministic top-2 combine ------------------------------
__global__ void combine_kernel(float* __restrict__ out) {
    int i = blockIdx.x * blockDim.x + threadIdx.x;   // over M_TOK*HIDDEN/4
    const float4* d = (const float4*)g_down;
    int tok = i >> 8;          // HIDDEN/4 = 256 float4 per row
    int c   = i & 255;
    float4 a = d[(size_t)(tok * 2)     * 256 + c];
    float4 b = d[(size_t)(tok * 2 + 1) * 256 + c];
    float4 r;
    r.x = a.x + b.x; r.y = a.y + b.y; r.z = a.z + b.z; r.w = a.w + b.w;
    ((float4*)out)[i] = r;
}

// ---------------- launch ---------------------------------------------------
extern "C" void kernel_launch(void* const* d_in, const int* in_sizes, int n_in,
                              void* d_out, int out_size) {
    const float* hs   = (const float*)d_in[0];  // [2,1024,1024]
    const int*   ridx = (const int*)  d_in[1];  // [2048,2]
    const float* rw   = (const float*)d_in[2];  // [2048,8]
    const float* gup  = (const float*)d_in[3];  // [8,1024,2048]
    const float* gupb = (const float*)d_in[4];  // [8,2048]
    const float* dwn  = (const float*)d_in[5];  // [8,1024,1024]
    const float* dwnb = (const float*)d_in[6];  // [8,1024]
    float* out = (float*)d_out;

    route_kernel<<<1, 256>>>(ridx, rw);
    dim3 grid1(MAX_TILES, N_GU / 128);    // (40, 16)
    gemm1_kernel<<<grid1, 256>>>(hs, gup, gupb);
    dim3 grid2(MAX_TILES, HIDDEN / 128);  // (40, 8)
    gemm2_kernel<<<grid2, 256>>>(dwn, dwnb);
    combine_kernel<<<M_TOK * (HIDDEN / 4) / 256, 256>>>(out);
}

// round 3
// speedup vs baseline: 1.8326x; 1.8326x over previous
#include <cuda_runtime.h>
#include <cuda_bf16.h>
#include <cstdint>

#define NUM_EXPERTS 8
#define HIDDEN     1024
#define INTER      1024
#define M_TOK      2048
#define NSLOT      4096        // M_TOK * TOPK
#define N_GU       2048        // 2*INTER
#define MAX_TILES  40

// ---------------- device scratch ----------------
__device__ int   g_perm[NSLOT];
__device__ float g_w[NSLOT];
__device__ int4  g_work[MAX_TILES];
__device__ float g_inter[(size_t)NSLOT * INTER];
__device__ float g_down [(size_t)NSLOT * HIDDEN];

// ---------------- routing ----------------
__global__ void route_kernel(const int* __restrict__ ridx,
                             const float* __restrict__ rw) {
    __shared__ int cnt[NUM_EXPERTS];
    __shared__ int ofs[NUM_EXPERTS];
    __shared__ int cur[NUM_EXPERTS];
    int t = threadIdx.x;
    if (t < NUM_EXPERTS) cnt[t] = 0;
    __syncthreads();
    for (int s = t; s < NSLOT; s += blockDim.x)
        atomicAdd(&cnt[ridx[s]], 1);
    __syncthreads();
    if (t == 0) {
        int acc = 0;
        for (int e = 0; e < NUM_EXPERTS; e++) { ofs[e] = acc; cur[e] = acc; acc += cnt[e]; }
    }
    __syncthreads();
    for (int s = t; s < NSLOT; s += blockDim.x) {
        int e = ridx[s];
        int p = atomicAdd(&cur[e], 1);
        g_perm[p] = s;
        g_w[p]    = rw[(s >> 1) * NUM_EXPERTS + e];
    }
    if (t == 0) {
        int n = 0;
        for (int e = 0; e < NUM_EXPERTS; e++)
            for (int r = 0; r < cnt[e]; r += 128) {
                g_work[n] = make_int4(e, ofs[e] + r, min(128, cnt[e] - r), 0);
                n++;
            }
        for (; n < MAX_TILES; n++) g_work[n] = make_int4(0, 0, 0, 0);
    }
}

// ---------------- MMA helpers ----------------
__device__ __forceinline__ void ldsm4(uint32_t a, uint32_t* r) {
    asm volatile("ldmatrix.sync.aligned.m8n8.x4.shared.b16 {%0,%1,%2,%3},[%4];\n"
        : "=r"(r[0]), "=r"(r[1]), "=r"(r[2]), "=r"(r[3]) : "r"(a));
}
__device__ __forceinline__ void ldsm4t(uint32_t a, uint32_t* r) {
    asm volatile("ldmatrix.sync.aligned.m8n8.x4.trans.shared.b16 {%0,%1,%2,%3},[%4];\n"
        : "=r"(r[0]), "=r"(r[1]), "=r"(r[2]), "=r"(r[3]) : "r"(a));
}
__device__ __forceinline__ void mma16816(float* c, const uint32_t* a, uint32_t b0, uint32_t b1) {
    asm volatile("mma.sync.aligned.m16n8k16.row.col.f32.bf16.bf16.f32 "
        "{%0,%1,%2,%3},{%4,%5,%6,%7},{%8,%9},{%0,%1,%2,%3};\n"
        : "+f"(c[0]), "+f"(c[1]), "+f"(c[2]), "+f"(c[3])
        : "r"(a[0]), "r"(a[1]), "r"(a[2]), "r"(a[3]), "r"(b0), "r"(b1));
}
__device__ __forceinline__ void splitp(float x, float y, uint32_t& hi, uint32_t& lo) {
    __nv_bfloat16 xh = __float2bfloat16_rn(x), yh = __float2bfloat16_rn(y);
    __nv_bfloat16 xl = __float2bfloat16_rn(x - __bfloat162float(xh));
    __nv_bfloat16 yl = __float2bfloat16_rn(y - __bfloat162float(yh));
    hi = (uint32_t)__bfloat16_as_ushort(xh) | ((uint32_t)__bfloat16_as_ushort(yh) << 16);
    lo = (uint32_t)__bfloat16_as_ushort(xl) | ((uint32_t)__bfloat16_as_ushort(yl) << 16);
}
__device__ __forceinline__ float swiglu(float g, float u) {
    g = fminf(g, 7.0f);
    u = fminf(fmaxf(u, -7.0f), 7.0f);
    float glu = g / (1.0f + __expf(-1.702f * g));
    return (u + 1.0f) * glu;
}

#define LDA 40     // padded A smem stride (bf16 elems) -> conflict-free ldmatrix
#define LDB 136    // padded B smem stride

// ---------------- GEMM1: x @ Wgu[e] (+bias, SwiGLU) -> g_inter -------------
__global__ __launch_bounds__(256, 1)
void gemm1_kernel(const float* __restrict__ x,
                  const float* __restrict__ W,      // [E,1024,2048]
                  const float* __restrict__ bias) { // [E,2048]
    int4 wk = g_work[blockIdx.x];
    int rows = wk.z;
    if (rows == 0) return;
    int e = wk.x, rowStart = wk.y;
    int n0 = blockIdx.y * 128;

    __shared__ uint16_t Ah[128 * LDA], Al[128 * LDA];
    __shared__ uint16_t Bh[32 * LDB],  Bl[32 * LDB];

    int tid = threadIdx.x, lane = tid & 31, wid = tid >> 5;

    // ---- gmem loaders ----
    int arow = tid >> 1;
    bool av = arow < rows;
    const float* aPtr;
    { int rr = rowStart + (av ? arow : 0);
      int slot = g_perm[rr];
      aPtr = x + (size_t)(slot >> 1) * HIDDEN + (tid & 1) * 16; }
    const float* bPtr = W + (size_t)e * HIDDEN * N_GU + (size_t)(tid >> 3) * N_GU
                          + n0 + (tid & 7) * 16;

    float4 aR[4], bR[4];
    #pragma unroll
    for (int i = 0; i < 4; i++) {
        aR[i] = av ? *(const float4*)(aPtr + 4 * i) : make_float4(0, 0, 0, 0);
        bR[i] = *(const float4*)(bPtr + 4 * i);
    }

    uint32_t sAh = (uint32_t)__cvta_generic_to_shared(Ah);
    uint32_t sAl = (uint32_t)__cvta_generic_to_shared(Al);
    uint32_t sBh = (uint32_t)__cvta_generic_to_shared(Bh);
    uint32_t sBl = (uint32_t)__cvta_generic_to_shared(Bl);

    int wm = wid & 3, wn = wid >> 2;
    int mb = wm * 32, nb = wn * 64;
    int fr = (lane & 7) + ((lane >> 3) & 1) * 8;
    int fc = (lane >> 4) * 8;

    float acc[2][8][4];
    #pragma unroll
    for (int a = 0; a < 2; a++)
        #pragma unroll
        for (int b = 0; b < 8; b++)
            #pragma unroll
            for (int c = 0; c < 4; c++) acc[a][b][c] = 0.f;

    for (int kk = 0; kk < HIDDEN; kk += 32) {
        // store staged tile (convert + split)
        {
            int ac = (tid & 1) * 16;
            int bro = tid >> 3, bc = (tid & 7) * 16;
            #pragma unroll
            for (int i = 0; i < 4; i++) {
                uint32_t h0, l0, h1, l1;
                splitp(aR[i].x, aR[i].y, h0, l0);
                splitp(aR[i].z, aR[i].w, h1, l1);
                int o = arow * LDA + ac + 4 * i;
                *(uint32_t*)&Ah[o] = h0; *(uint32_t*)&Ah[o + 2] = h1;
                *(uint32_t*)&Al[o] = l0; *(uint32_t*)&Al[o + 2] = l1;
                splitp(bR[i].x, bR[i].y, h0, l0);
                splitp(bR[i].z, bR[i].w, h1, l1);
                int p = bro * LDB + bc + 4 * i;
                *(uint32_t*)&Bh[p] = h0; *(uint32_t*)&Bh[p + 2] = h1;
                *(uint32_t*)&Bl[p] = l0; *(uint32_t*)&Bl[p + 2] = l1;
            }
        }
        __syncthreads();
        if (kk + 32 < HIDDEN) {
            #pragma unroll
            for (int i = 0; i < 4; i++) {
                aR[i] = av ? *(const float4*)(aPtr + kk + 32 + 4 * i) : make_float4(0, 0, 0, 0);
                bR[i] = *(const float4*)(bPtr + (size_t)(kk + 32) * N_GU + 4 * i);
            }
        }
        // compute
        #pragma unroll
        for (int ks = 0; ks < 2; ks++) {
            uint32_t ah[2][4], al_[2][4];
            #pragma unroll
            for (int t2 = 0; t2 < 2; t2++) {
                uint32_t off = (uint32_t)(((mb + t2 * 16 + fr) * LDA + ks * 16 + fc) * 2);
                ldsm4(sAh + off, ah[t2]);
                ldsm4(sAl + off, al_[t2]);
            }
            #pragma unroll
            for (int p = 0; p < 4; p++) {
                uint32_t bh[4], bl_[4];
                uint32_t off = (uint32_t)(((ks * 16 + fr) * LDB + nb + p * 16 + fc) * 2);
                ldsm4t(sBh + off, bh);
                ldsm4t(sBl + off, bl_);
                #pragma unroll
                for (int t2 = 0; t2 < 2; t2++) {
                    mma16816(acc[t2][2 * p],     ah[t2],  bh[0],  bh[1]);
                    mma16816(acc[t2][2 * p],     ah[t2],  bl_[0], bl_[1]);
                    mma16816(acc[t2][2 * p],     al_[t2], bh[0],  bh[1]);
                    mma16816(acc[t2][2 * p + 1], ah[t2],  bh[2],  bh[3]);
                    mma16816(acc[t2][2 * p + 1], ah[t2],  bl_[2], bl_[3]);
                    mma16816(acc[t2][2 * p + 1], al_[t2], bh[2],  bh[3]);
                }
            }
        }
        __syncthreads();
    }

    // epilogue: bias + SwiGLU -> g_inter
    const float* bp = bias + e * N_GU + n0;
    int r4 = lane >> 2, c2 = (lane & 3) * 2;
    #pragma unroll
    for (int t2 = 0; t2 < 2; t2++) {
        int lr0 = mb + t2 * 16 + r4;
        int lr1 = lr0 + 8;
        float* o0 = (lr0 < rows) ? g_inter + (size_t)(rowStart + lr0) * INTER : nullptr;
        float* o1 = (lr1 < rows) ? g_inter + (size_t)(rowStart + lr1) * INTER : nullptr;
        #pragma unroll
        for (int p = 0; p < 4; p++)
            #pragma unroll
            for (int nt = 0; nt < 2; nt++) {
                int nloc = nb + p * 16 + nt * 8 + c2;
                float2 bb = *(const float2*)(bp + nloc);
                float* c = acc[t2][2 * p + nt];
                int ic = (n0 + nloc) >> 1;
                if (o0) o0[ic] = swiglu(c[0] + bb.x, c[1] + bb.y);
                if (o1) o1[ic] = swiglu(c[2] + bb.x, c[3] + bb.y);
            }
    }
}

// ---------------- GEMM2: inter @ Wd[e] (+bias)*w -> g_down[slot] -----------
__global__ __launch_bounds__(256, 1)
void gemm2_kernel(const float* __restrict__ W,      // [E,1024,1024]
                  const float* __restrict__ bias) { // [E,1024]
    int4 wk = g_work[blockIdx.x];
    int rows = wk.z;
    if (rows == 0) return;
    int e = wk.x, rowStart = wk.y;
    int n0 = blockIdx.y * 128;

    __shared__ uint16_t Ah[128 * LDA], Al[128 * LDA];
    __shared__ uint16_t Bh[32 * LDB],  Bl[32 * LDB];

    int tid = threadIdx.x, lane = tid & 31, wid = tid >> 5;

    int arow = tid >> 1;
    bool av = arow < rows;
    const float* aPtr = g_inter + (size_t)(rowStart + (av ? arow : 0)) * INTER + (tid & 1) * 16;
    const float* bPtr = W + (size_t)e * INTER * HIDDEN + (size_t)(tid >> 3) * HIDDEN
                          + n0 + (tid & 7) * 16;

    float4 aR[4], bR[4];
    #pragma unroll
    for (int i = 0; i < 4; i++) {
        aR[i] = av ? *(const float4*)(aPtr + 4 * i) : make_float4(0, 0, 0, 0);
        bR[i] = *(const float4*)(bPtr + 4 * i);
    }

    uint32_t sAh = (uint32_t)__cvta_generic_to_shared(Ah);
    uint32_t sAl = (uint32_t)__cvta_generic_to_shared(Al);
    uint32_t sBh = (uint32_t)__cvta_generic_to_shared(Bh);
    uint32_t sBl = (uint32_t)__cvta_generic_to_shared(Bl);

    int wm = wid & 3, wn = wid >> 2;
    int mb = wm * 32, nb = wn * 64;
    int fr = (lane & 7) + ((lane >> 3) & 1) * 8;
    int fc = (lane >> 4) * 8;

    float acc[2][8][4];
    #pragma unroll
    for (int a = 0; a < 2; a++)
        #pragma unroll
        for (int b = 0; b < 8; b++)
            #pragma unroll
            for (int c = 0; c < 4; c++) acc[a][b][c] = 0.f;

    for (int kk = 0; kk < INTER; kk += 32) {
        {
            int ac = (tid & 1) * 16;
            int bro = tid >> 3, bc = (tid & 7) * 16;
            #pragma unroll
            for (int i = 0; i < 4; i++) {
                uint32_t h0, l0, h1, l1;
                splitp(aR[i].x, aR[i].y, h0, l0);
                splitp(aR[i].z, aR[i].w, h1, l1);
                int o = arow * LDA + ac + 4 * i;
                *(uint32_t*)&Ah[o] = h0; *(uint32_t*)&Ah[o + 2] = h1;
                *(uint32_t*)&Al[o] = l0; *(uint32_t*)&Al[o + 2] = l1;
                splitp(bR[i].x, bR[i].y, h0, l0);
                splitp(bR[i].z, bR[i].w, h1, l1);
                int p = bro * LDB + bc + 4 * i;
                *(uint32_t*)&Bh[p] = h0; *(uint32_t*)&Bh[p + 2] = h1;
                *(uint32_t*)&Bl[p] = l0; *(uint32_t*)&Bl[p + 2] = l1;
            }
        }
        __syncthreads();
        if (kk + 32 < INTER) {
            #pragma unroll
            for (int i = 0; i < 4; i++) {
                aR[i] = av ? *(const float4*)(aPtr + kk + 32 + 4 * i) : make_float4(0, 0, 0, 0);
                bR[i] = *(const float4*)(bPtr + (size_t)(kk + 32) * HIDDEN + 4 * i);
            }
        }
        #pragma unroll
        for (int ks = 0; ks < 2; ks++) {
            uint32_t ah[2][4], al_[2][4];
            #pragma unroll
            for (int t2 = 0; t2 < 2; t2++) {
                uint32_t off = (uint32_t)(((mb + t2 * 16 + fr) * LDA + ks * 16 + fc) * 2);
                ldsm4(sAh + off, ah[t2]);
                ldsm4(sAl + off, al_[t2]);
            }
            #pragma unroll
            for (int p = 0; p < 4; p++) {
                uint32_t bh[4], bl_[4];
                uint32_t off = (uint32_t)(((ks * 16 + fr) * LDB + nb + p * 16 + fc) * 2);
                ldsm4t(sBh + off, bh);
                ldsm4t(sBl + off, bl_);
                #pragma unroll
                for (int t2 = 0; t2 < 2; t2++) {
                    mma16816(acc[t2][2 * p],     ah[t2],  bh[0],  bh[1]);
                    mma16816(acc[t2][2 * p],     ah[t2],  bl_[0], bl_[1]);
                    mma16816(acc[t2][2 * p],     al_[t2], bh[0],  bh[1]);
                    mma16816(acc[t2][2 * p + 1], ah[t2],  bh[2],  bh[3]);
                    mma16816(acc[t2][2 * p + 1], ah[t2],  bl_[2], bl_[3]);
                    mma16816(acc[t2][2 * p + 1], al_[t2], bh[2],  bh[3]);
                }
            }
        }
        __syncthreads();
    }

    // epilogue: (acc + bias) * routing_weight -> g_down[slot]
    const float* bp = bias + e * HIDDEN + n0;
    int r4 = lane >> 2, c2 = (lane & 3) * 2;
    #pragma unroll
    for (int t2 = 0; t2 < 2; t2++) {
        int lr0 = mb + t2 * 16 + r4;
        int lr1 = lr0 + 8;
        int   s0 = 0, s1 = 0;
        float w0 = 0.f, w1 = 0.f;
        bool v0 = lr0 < rows, v1 = lr1 < rows;
        if (v0) { int r = rowStart + lr0; s0 = g_perm[r]; w0 = g_w[r]; }
        if (v1) { int r = rowStart + lr1; s1 = g_perm[r]; w1 = g_w[r]; }
        #pragma unroll
        for (int p = 0; p < 4; p++)
            #pragma unroll
            for (int nt = 0; nt < 2; nt++) {
                int nloc = nb + p * 16 + nt * 8 + c2;
                float2 bb = *(const float2*)(bp + nloc);
                float* c = acc[t2][2 * p + nt];
                if (v0) {
                    float2 v = make_float2((c[0] + bb.x) * w0, (c[1] + bb.y) * w0);
                    *(float2*)(g_down + (size_t)s0 * HIDDEN + n0 + nloc) = v;
                }
                if (v1) {
                    float2 v = make_float2((c[2] + bb.x) * w1, (c[3] + bb.y) * w1);
                    *(float2*)(g_down + (size_t)s1 * HIDDEN + n0 + nloc) = v;
                }
            }
    }
}

// ---------------- deterministic top-2 combine ------------------------------
__global__ void combine_kernel(float* __restrict__ out) {
    int i = blockIdx.x * blockDim.x + threadIdx.x;
    const float4* d = (const float4*)g_down;
    int tok = i >> 8;
    int c   = i & 255;
    float4 a = d[(size_t)(tok * 2)     * 256 + c];
    float4 b = d[(size_t)(tok * 2 + 1) * 256 + c];
    float4 r;
    r.x = a.x + b.x; r.y = a.y + b.y; r.z = a.z + b.z; r.w = a.w + b.w;
    ((float4*)out)[i] = r;
}

// ---------------- launch ---------------------------------------------------
extern "C" void kernel_launch(void* const* d_in, const int* in_sizes, int n_in,
                              void* d_out, int out_size) {
    const float* hs   = (const float*)d_in[0];
    const int*   ridx = (const int*)  d_in[1];
    const float* rw   = (const float*)d_in[2];
    const float* gup  = (const float*)d_in[3];
    const float* gupb = (const float*)d_in[4];
    const float* dwn  = (const float*)d_in[5];
    const float* dwnb = (const float*)d_in[6];
    float* out = (float*)d_out;

    route_kernel<<<1, 256>>>(ridx, rw);
    dim3 grid1(MAX_TILES, N_GU / 128);    // (40, 16)
    gemm1_kernel<<<grid1, 256>>>(hs, gup, gupb);
    dim3 grid2(MAX_TILES, HIDDEN / 128);  // (40, 8)
    gemm2_kernel<<<grid2, 256>>>(dwn, dwnb);
    combine_kernel<<<M_TOK * (HIDDEN / 4) / 256, 256>>>(out);
}

// round 7
// speedup vs baseline: 2.0896x; 1.1402x over previous
#include <cuda_runtime.h>
#include <cuda_bf16.h>
#include <cstdint>

typedef __nv_bfloat16 bf16;

#define NUM_EXPERTS 8
#define HIDDEN     1024
#define INTER      1024
#define M_TOK      2048
#define NSLOT      4096
#define N_GU       2048
#define MAX_TILES  40

// ---------------- device scratch ----------------
__device__ int   g_perm[NSLOT];
__device__ float g_w[NSLOT];
__device__ int4  g_work[MAX_TILES];
__device__ bf16  g_w1h[(size_t)NUM_EXPERTS * HIDDEN * N_GU];
__device__ bf16  g_w1l[(size_t)NUM_EXPERTS * HIDDEN * N_GU];
__device__ bf16  g_w2h[(size_t)NUM_EXPERTS * INTER * HIDDEN];
__device__ bf16  g_w2l[(size_t)NUM_EXPERTS * INTER * HIDDEN];
__device__ bf16  g_xh[(size_t)M_TOK * HIDDEN];
__device__ bf16  g_xl[(size_t)M_TOK * HIDDEN];
__device__ bf16  g_ih[(size_t)NSLOT * INTER];
__device__ bf16  g_il[(size_t)NSLOT * INTER];
__device__ float g_down[(size_t)NSLOT * HIDDEN];

// ---------------- routing ----------------
__global__ void route_kernel(const int* __restrict__ ridx,
                             const float* __restrict__ rw) {
    __shared__ int cnt[NUM_EXPERTS];
    __shared__ int ofs[NUM_EXPERTS];
    __shared__ int cur[NUM_EXPERTS];
    int t = threadIdx.x;
    if (t < NUM_EXPERTS) cnt[t] = 0;
    __syncthreads();
    for (int s = t; s < NSLOT; s += blockDim.x)
        atomicAdd(&cnt[ridx[s]], 1);
    __syncthreads();
    if (t == 0) {
        int acc = 0;
        for (int e = 0; e < NUM_EXPERTS; e++) { ofs[e] = acc; cur[e] = acc; acc += cnt[e]; }
    }
    __syncthreads();
    for (int s = t; s < NSLOT; s += blockDim.x) {
        int e = ridx[s];
        int p = atomicAdd(&cur[e], 1);
        g_perm[p] = s;
        g_w[p]    = rw[(s >> 1) * NUM_EXPERTS + e];
    }
    if (t == 0) {
        int n = 0;
        for (int e = 0; e < NUM_EXPERTS; e++)
            for (int r = 0; r < cnt[e]; r += 128) {
                g_work[n] = make_int4(e, ofs[e] + r, min(128, cnt[e] - r), 0);
                n++;
            }
        for (; n < MAX_TILES; n++) g_work[n] = make_int4(0, 0, 0, 0);
    }
}

// ---------------- fp32 -> bf16 (hi, lo) split ----------------
__device__ __forceinline__ void split1(float x, uint16_t& h, uint16_t& l) {
    __nv_bfloat16 xh = __float2bfloat16_rn(x);
    h = __bfloat16_as_ushort(xh);
    l = __bfloat16_as_ushort(__float2bfloat16_rn(x - __bfloat162float(xh)));
}

// WHICH: 0 -> w1, 1 -> w2, 2 -> x. Destinations resolved IN DEVICE CODE
// (passing __device__ symbols as kernel args from host is invalid — R4/R5 bug).
template<int WHICH>
__global__ void split_kernel(const float4* __restrict__ in, int n4) {
    int i = blockIdx.x * blockDim.x + threadIdx.x;
    if (i >= n4) return;
    uint2* oh; uint2* ol;
    if (WHICH == 0)      { oh = (uint2*)g_w1h; ol = (uint2*)g_w1l; }
    else if (WHICH == 1) { oh = (uint2*)g_w2h; ol = (uint2*)g_w2l; }
    else                 { oh = (uint2*)g_xh;  ol = (uint2*)g_xl;  }
    float4 v = in[i];
    uint16_t h0, h1, h2, h3, l0, l1, l2, l3;
    split1(v.x, h0, l0); split1(v.y, h1, l1);
    split1(v.z, h2, l2); split1(v.w, h3, l3);
    oh[i] = make_uint2((uint32_t)h0 | ((uint32_t)h1 << 16), (uint32_t)h2 | ((uint32_t)h3 << 16));
    ol[i] = make_uint2((uint32_t)l0 | ((uint32_t)l1 << 16), (uint32_t)l2 | ((uint32_t)l3 << 16));
}

// ---------------- MMA helpers ----------------
__device__ __forceinline__ void ldsm4(uint32_t a, uint32_t* r) {
    asm volatile("ldmatrix.sync.aligned.m8n8.x4.shared.b16 {%0,%1,%2,%3},[%4];\n"
        : "=r"(r[0]), "=r"(r[1]), "=r"(r[2]), "=r"(r[3]) : "r"(a));
}
__device__ __forceinline__ void ldsm4t(uint32_t a, uint32_t* r) {
    asm volatile("ldmatrix.sync.aligned.m8n8.x4.trans.shared.b16 {%0,%1,%2,%3},[%4];\n"
        : "=r"(r[0]), "=r"(r[1]), "=r"(r[2]), "=r"(r[3]) : "r"(a));
}
__device__ __forceinline__ void mma16816(float* c, const uint32_t* a, uint32_t b0, uint32_t b1) {
    asm volatile("mma.sync.aligned.m16n8k16.row.col.f32.bf16.bf16.f32 "
        "{%0,%1,%2,%3},{%4,%5,%6,%7},{%8,%9},{%0,%1,%2,%3};\n"
        : "+f"(c[0]), "+f"(c[1]), "+f"(c[2]), "+f"(c[3])
        : "r"(a[0]), "r"(a[1]), "r"(a[2]), "r"(a[3]), "r"(b0), "r"(b1));
}
__device__ __forceinline__ float swiglu(float g, float u) {
    g = fminf(g, 7.0f);
    u = fminf(fmaxf(u, -7.0f), 7.0f);
    return (u + 1.0f) * (g / (1.0f + __expf(-1.702f * g)));
}

#define LDA 40     // A smem stride (bf16 elems): 32 data + 8 pad
#define LDB 136    // B smem stride: 128 data + 8 pad

// ---------------- grouped GEMM (G1: gate_up+SwiGLU, G2: down) ----------------
template<bool G1>
__global__ void __launch_bounds__(256, 1)
gemm_kernel(const float* __restrict__ bias) {
    int4 wk = g_work[blockIdx.x];
    int rows = wk.z;
    if (rows == 0) return;
    int e = wk.x, rowStart = wk.y;
    int n0 = blockIdx.y * 128;
    const int NST = G1 ? N_GU : HIDDEN;

    __shared__ uint16_t Ah[128 * LDA], Al[128 * LDA];
    __shared__ uint16_t Bh[32 * LDB],  Bl[32 * LDB];

    int tid = threadIdx.x, lane = tid & 31, wid = tid >> 5;

    // ---- global source pointers (pre-split bf16) ----
    int arow = tid >> 1, aq = tid & 1;          // A: 2 thr/row, 16 elems each
    bool av = arow < rows;
    int r_idx = rowStart + (av ? arow : 0);
    const bf16 *aH, *aL;
    if (G1) {
        int tok = g_perm[r_idx] >> 1;
        aH = g_xh + (size_t)tok * HIDDEN + aq * 16;
        aL = g_xl + (size_t)tok * HIDDEN + aq * 16;
    } else {
        aH = g_ih + (size_t)r_idx * INTER + aq * 16;
        aL = g_il + (size_t)r_idx * INTER + aq * 16;
    }
    int bk = tid >> 3, bc = (tid & 7) * 16;     // B: 8 thr/row, 16 elems each
    const bf16* bH = (G1 ? g_w1h : g_w2h) + (size_t)e * 1024 * NST + (size_t)bk * NST + n0 + bc;
    const bf16* bL = (G1 ? g_w1l : g_w2l) + (size_t)e * 1024 * NST + (size_t)bk * NST + n0 + bc;

    uint32_t sAh = (uint32_t)__cvta_generic_to_shared(Ah);
    uint32_t sAl = (uint32_t)__cvta_generic_to_shared(Al);
    uint32_t sBh = (uint32_t)__cvta_generic_to_shared(Bh);
    uint32_t sBl = (uint32_t)__cvta_generic_to_shared(Bl);

    int wm = wid & 3, wn = wid >> 2;
    int mb = wm * 32, nb = wn * 64;
    int fr = (lane & 7) + ((lane >> 3) & 1) * 8;
    int fc = (lane >> 4) * 8;

    float acc[2][8][4];
    #pragma unroll
    for (int a = 0; a < 2; a++)
        #pragma unroll
        for (int b = 0; b < 8; b++)
            #pragma unroll
            for (int c = 0; c < 4; c++) acc[a][b][c] = 0.f;

    const uint4 Z4 = make_uint4(0, 0, 0, 0);
    uint4 aRh[2], aRl[2], bRh[2], bRl[2];
    #pragma unroll
    for (int i = 0; i < 2; i++) {
        aRh[i] = av ? *(const uint4*)(aH + 8 * i) : Z4;
        aRl[i] = av ? *(const uint4*)(aL + 8 * i) : Z4;
        bRh[i] = *(const uint4*)(bH + 8 * i);
        bRl[i] = *(const uint4*)(bL + 8 * i);
    }

    #pragma unroll 1
    for (int kk = 0; kk < 1024; kk += 32) {
        // ---- store staged tile (direct bf16, no conversion) ----
        {
            int ao = arow * LDA + aq * 16;
            *(uint4*)&Ah[ao]     = aRh[0];
            *(uint4*)&Ah[ao + 8] = aRh[1];
            *(uint4*)&Al[ao]     = aRl[0];
            *(uint4*)&Al[ao + 8] = aRl[1];
            int bo = bk * LDB + bc;
            *(uint4*)&Bh[bo]     = bRh[0];
            *(uint4*)&Bh[bo + 8] = bRh[1];
            *(uint4*)&Bl[bo]     = bRl[0];
            *(uint4*)&Bl[bo + 8] = bRl[1];
        }
        __syncthreads();
        // prefetch next k-block
        if (kk + 32 < 1024) {
            int k2 = kk + 32;
            #pragma unroll
            for (int i = 0; i < 2; i++) {
                aRh[i] = av ? *(const uint4*)(aH + k2 + 8 * i) : Z4;
                aRl[i] = av ? *(const uint4*)(aL + k2 + 8 * i) : Z4;
                bRh[i] = *(const uint4*)(bH + (size_t)k2 * NST + 8 * i);
                bRl[i] = *(const uint4*)(bL + (size_t)k2 * NST + 8 * i);
            }
        }
        // ---- compute (identical to proven R2) ----
        #pragma unroll
        for (int ks = 0; ks < 2; ks++) {
            uint32_t ah[2][4], al2[2][4];
            #pragma unroll
            for (int t2 = 0; t2 < 2; t2++) {
                uint32_t off = (uint32_t)(((mb + t2 * 16 + fr) * LDA + ks * 16 + fc) * 2);
                ldsm4(sAh + off, ah[t2]);
                ldsm4(sAl + off, al2[t2]);
            }
            #pragma unroll
            for (int p = 0; p < 4; p++) {
                uint32_t bh[4], bl2[4];
                uint32_t off = (uint32_t)(((ks * 16 + fr) * LDB + nb + p * 16 + fc) * 2);
                ldsm4t(sBh + off, bh);
                ldsm4t(sBl + off, bl2);
                #pragma unroll
                for (int t2 = 0; t2 < 2; t2++) {
                    mma16816(acc[t2][2 * p],     ah[t2],  bh[0],  bh[1]);
                    mma16816(acc[t2][2 * p],     ah[t2],  bl2[0], bl2[1]);
                    mma16816(acc[t2][2 * p],     al2[t2], bh[0],  bh[1]);
                    mma16816(acc[t2][2 * p + 1], ah[t2],  bh[2],  bh[3]);
                    mma16816(acc[t2][2 * p + 1], ah[t2],  bl2[2], bl2[3]);
                    mma16816(acc[t2][2 * p + 1], al2[t2], bh[2],  bh[3]);
                }
            }
        }
        __syncthreads();
    }

    // ---- epilogue ----
    int r4 = lane >> 2, c2 = (lane & 3) * 2;
    if (G1) {
        const float* bp = bias + e * N_GU + n0;
        #pragma unroll
        for (int t2 = 0; t2 < 2; t2++) {
            int lr0 = mb + t2 * 16 + r4;
            int lr1 = lr0 + 8;
            bool v0 = lr0 < rows, v1 = lr1 < rows;
            size_t o0 = v0 ? (size_t)(rowStart + lr0) * INTER : 0;
            size_t o1 = v1 ? (size_t)(rowStart + lr1) * INTER : 0;
            #pragma unroll
            for (int p = 0; p < 4; p++)
                #pragma unroll
                for (int nt = 0; nt < 2; nt++) {
                    int nloc = nb + p * 16 + nt * 8 + c2;
                    float2 bb = *(const float2*)(bp + nloc);
                    float* c = acc[t2][2 * p + nt];
                    int ic = (n0 + nloc) >> 1;
                    if (v0) {
                        float v = swiglu(c[0] + bb.x, c[1] + bb.y);
                        uint16_t h, l; split1(v, h, l);
                        *(uint16_t*)&g_ih[o0 + ic] = h;
                        *(uint16_t*)&g_il[o0 + ic] = l;
                    }
                    if (v1) {
                        float v = swiglu(c[2] + bb.x, c[3] + bb.y);
                        uint16_t h, l; split1(v, h, l);
                        *(uint16_t*)&g_ih[o1 + ic] = h;
                        *(uint16_t*)&g_il[o1 + ic] = l;
                    }
                }
        }
    } else {
        const float* bp = bias + e * HIDDEN + n0;
        #pragma unroll
        for (int t2 = 0; t2 < 2; t2++) {
            int lr0 = mb + t2 * 16 + r4;
            int lr1 = lr0 + 8;
            bool v0 = lr0 < rows, v1 = lr1 < rows;
            int s0 = 0, s1 = 0; float w0 = 0.f, w1 = 0.f;
            if (v0) { int r = rowStart + lr0; s0 = g_perm[r]; w0 = g_w[r]; }
            if (v1) { int r = rowStart + lr1; s1 = g_perm[r]; w1 = g_w[r]; }
            #pragma unroll
            for (int p = 0; p < 4; p++)
                #pragma unroll
                for (int nt = 0; nt < 2; nt++) {
                    int nloc = nb + p * 16 + nt * 8 + c2;
                    float2 bb = *(const float2*)(bp + nloc);
                    float* c = acc[t2][2 * p + nt];
                    if (v0) {
                        float2 v = make_float2((c[0] + bb.x) * w0, (c[1] + bb.y) * w0);
                        *(float2*)(g_down + (size_t)s0 * HIDDEN + n0 + nloc) = v;
                    }
                    if (v1) {
                        float2 v = make_float2((c[2] + bb.x) * w1, (c[3] + bb.y) * w1);
                        *(float2*)(g_down + (size_t)s1 * HIDDEN + n0 + nloc) = v;
                    }
                }
        }
    }
}

// ---------------- deterministic top-2 combine ------------------------------
__global__ void combine_kernel(float* __restrict__ out) {
    int i = blockIdx.x * blockDim.x + threadIdx.x;
    const float4* d = (const float4*)g_down;
    int tok = i >> 8;
    int c   = i & 255;
    float4 a = d[(size_t)(tok * 2)     * 256 + c];
    float4 b = d[(size_t)(tok * 2 + 1) * 256 + c];
    float4 r;
    r.x = a.x + b.x; r.y = a.y + b.y; r.z = a.z + b.z; r.w = a.w + b.w;
    ((float4*)out)[i] = r;
}

// ---------------- launch ---------------------------------------------------
extern "C" void kernel_launch(void* const* d_in, const int* in_sizes, int n_in,
                              void* d_out, int out_size) {
    const float* hs   = (const float*)d_in[0];
    const int*   ridx = (const int*)  d_in[1];
    const float* rw   = (const float*)d_in[2];
    const float* gup  = (const float*)d_in[3];
    const float* gupb = (const float*)d_in[4];
    const float* dwn  = (const float*)d_in[5];
    const float* dwnb = (const float*)d_in[6];
    float* out = (float*)d_out;

    route_kernel<<<1, 256>>>(ridx, rw);

    // pre-split fp32 -> bf16 hi/lo (destinations bound inside device code)
    {
        int n4 = NUM_EXPERTS * HIDDEN * N_GU / 4;
        split_kernel<0><<<n4 / 256, 256>>>((const float4*)gup, n4);
    }
    {
        int n4 = NUM_EXPERTS * INTER * HIDDEN / 4;
        split_kernel<1><<<n4 / 256, 256>>>((const float4*)dwn, n4);
    }
    {
        int n4 = M_TOK * HIDDEN / 4;
        split_kernel<2><<<n4 / 256, 256>>>((const float4*)hs, n4);
    }

    dim3 grid1(MAX_TILES, N_GU / 128);    // (40, 16)
    gemm_kernel<true><<<grid1, 256>>>(gupb);
    dim3 grid2(MAX_TILES, HIDDEN / 128);  // (40, 8)
    gemm_kernel<false><<<grid2, 256>>>(dwnb);

    combine_kernel<<<M_TOK * (HIDDEN / 4) / 256, 256>>>(out);
}